// round 9
// baseline (speedup 1.0000x reference)
#include <cuda_runtime.h>
#include <cstdint>

// ---------------------------------------------------------------------------
// BCNet, tf32 mma.sync with pre-converted & k-permuted operands + cp.async.
//  passes: perm_cvt(v,q,Wv,Wq) -> G1 -> perm_cvt(g_v) -> G2 -> qh -> G3
//  k-permutation (within each 32-block): k = kk*8 + h*4 + t <->
//                                        kappa = t*8 + kk*2 + h
//  applied identically to A and B so contractions are unchanged; each
//  thread's mma fragments become contiguous 16B chunks (LDS.128).
//  R8: fix cp.async source address (was missing the +s4 segment offset).
// ---------------------------------------------------------------------------

#define B_   32
#define NV_  512
#define NQ_  128
#define VD_  2048
#define QD_  1024
#define HK_  1536
#define HO_  8

__device__ float g_at [(size_t)B_ * NV_ * VD_];      // perm/cvt v      134MB
__device__ float g_qt [(size_t)B_ * NQ_ * QD_];      // perm/cvt q       17MB
__device__ float g_wvt[(size_t)HK_ * VD_];           // perm/cvt Wv      13MB
__device__ float g_wqt[(size_t)HK_ * QD_];           // perm/cvt Wq       6MB
__device__ float g_v  [(size_t)B_ * NV_ * HK_];      // G1 out (plain)  100MB
__device__ float g_vtp[(size_t)B_ * NV_ * HK_];      // perm/cvt g_v    100MB
__device__ float g_q  [(size_t)B_ * NQ_ * HK_];      // G2 out (plain)   25MB
__device__ float g_qh [(size_t)B_ * HO_ * NQ_ * HK_];// perm/cvt q*h    201MB

#define BM 128
#define BN 128
#define KT 32
#define PROW 144                      // smem row stride bytes (36 floats)
#define A_BYTES (BM * PROW)           // 18432
#define STAGE_BYTES (2 * A_BYTES)     // 36864 (A then B)
#define NSTAGE 3
#define SMEM_BYTES (NSTAGE * STAGE_BYTES)   // 110592

__device__ __forceinline__ uint32_t rna(float x) {
    uint32_t y; asm("cvt.rna.tf32.f32 %0, %1;" : "=r"(y) : "f"(x)); return y;
}
__device__ __forceinline__ int korig(int kap) {     // kappa -> k (within 32)
    const int t = kap >> 3, kk = (kap >> 1) & 3, h = kap & 1;
    return kk * 8 + h * 4 + t;
}
__device__ __forceinline__ uint32_t smem_u32(const void* p) {
    uint32_t a;
    asm("{ .reg .u64 t; cvta.to.shared.u64 t, %1; cvt.u32.u64 %0, t; }"
        : "=r"(a) : "l"(p));
    return a;
}
__device__ __forceinline__ void cpa16(uint32_t dst, const void* src) {
    asm volatile("cp.async.cg.shared.global [%0], [%1], 16;"
                 :: "r"(dst), "l"(src) : "memory");
}
__device__ __forceinline__ void cpa_commit() {
    asm volatile("cp.async.commit_group;" ::: "memory");
}
__device__ __forceinline__ void cpa_wait1() {
    asm volatile("cp.async.wait_group 1;" ::: "memory");
}
__device__ __forceinline__ void mma8(float& d0, float& d1, float& d2, float& d3,
                                     uint32_t a0, uint32_t a1, uint32_t a2, uint32_t a3,
                                     uint32_t b0, uint32_t b1) {
    asm volatile(
        "mma.sync.aligned.m16n8k8.row.col.f32.tf32.tf32.f32 "
        "{%0,%1,%2,%3}, {%4,%5,%6,%7}, {%8,%9}, {%0,%1,%2,%3};"
        : "+f"(d0), "+f"(d1), "+f"(d2), "+f"(d3)
        : "r"(a0), "r"(a1), "r"(a2), "r"(a3), "r"(b0), "r"(b1));
}

// ------------------------- pre-pass: cvt + permute -------------------------
// dsel: 0->g_at, 1->g_qt, 2->g_wvt, 3->g_wqt, 4->g_vtp (src = g_v)
__global__ void __launch_bounds__(256)
perm_cvt(const float* __restrict__ src_in, int dsel, size_t n)
{
    const size_t base = ((size_t)blockIdx.x * blockDim.x + threadIdx.x) * 4;
    if (base >= n) return;
    const float* __restrict__ src = (dsel == 4) ? g_v : src_in;
    float* __restrict__ dst =
        (dsel == 0) ? g_at : (dsel == 1) ? g_qt :
        (dsel == 2) ? g_wvt : (dsel == 3) ? g_wqt : g_vtp;
    const size_t blk = base >> 5;
    const int off = (int)(base & 31);
    const float* s = src + blk * 32;
    uint4 o;
    o.x = rna(s[korig(off + 0)]);
    o.y = rna(s[korig(off + 1)]);
    o.z = rna(s[korig(off + 2)]);
    o.w = rna(s[korig(off + 3)]);
    *(uint4*)(dst + base) = o;
}

// pre-pass: g_qh[(z*8+h)*128+q][kap] = rna(g_q[z*128+q][k] * h_mat[h][k])
__global__ void __launch_bounds__(256)
qh_cvt(const float* __restrict__ h_mat)
{
    const size_t base = ((size_t)blockIdx.x * blockDim.x + threadIdx.x) * 4;
    if (base >= (size_t)B_ * HO_ * NQ_ * HK_) return;
    const size_t row = base / HK_;
    const int col = (int)(base % HK_);
    const int q = (int)(row & 127);
    const int h = (int)((row >> 7) & 7);
    const int z = (int)(row >> 10);
    const int blk = col >> 5, off = col & 31;
    const float* gr = g_q + ((size_t)z * NQ_ + q) * HK_ + blk * 32;
    const float* hr = h_mat + (size_t)h * HK_ + blk * 32;
    uint4 o;
    int k0 = korig(off + 0), k1 = korig(off + 1);
    int k2 = korig(off + 2), k3 = korig(off + 3);
    o.x = rna(gr[k0] * hr[k0]);
    o.y = rna(gr[k1] * hr[k1]);
    o.z = rna(gr[k2] * hr[k2]);
    o.w = rna(gr[k3] * hr[k3]);
    *(uint4*)(g_qh + base) = o;
}

// ------------------------------ GEMM kernel -------------------------------
// sel0: A=g_at, B=g_wvt, C=g_v, relu(acc+bias[n])
// sel1: A=g_qt, B=g_wqt, C=g_q, relu(acc+bias[n])
// sel2: A=g_vtp[z], B=g_qh[z], C=Cp scatter (+h_bias[h]), h=blockIdx.y
__global__ void __launch_bounds__(256)
gemm_mma(const float* __restrict__ bias, const float* __restrict__ h_bias,
         float* __restrict__ Cp, int Ntot, int K, int sel)
{
    extern __shared__ char smem[];
    const uint32_t smb = smem_u32(smem);

    const int tid   = threadIdx.x;
    const int wid   = tid >> 5;
    const int lane  = tid & 31;
    const int group = lane >> 2;
    const int tig   = lane & 3;
    const int warp_m = (wid & 1) * 64;
    const int warp_n = (wid >> 1) * 32;

    const int bm = blockIdx.x * BM;
    const int bn = blockIdx.y * BN;
    const int z  = blockIdx.z;
    const int mode = (sel == 2);

    const float* __restrict__ Abase =
        (sel == 0) ? g_at : (sel == 1) ? g_qt : g_vtp;
    const float* __restrict__ Bbase =
        (sel == 0) ? g_wvt : (sel == 1) ? g_wqt : g_qh;

    const float* __restrict__ Ag = Abase +
        ((size_t)(mode ? z * NV_ : 0) + bm) * K;
    const float* __restrict__ Bg = Bbase +
        ((size_t)(mode ? z * (HO_ * NQ_) : 0) + bn) * K;

    const int r0 = tid >> 3;
    const int s4 = (tid & 7) * 4;                 // segment offset in floats
    const uint32_t stg_off = (uint32_t)(r0 * PROW + s4 * 4);

    float acc[4][4][4];
#pragma unroll
    for (int i = 0; i < 4; ++i)
#pragma unroll
        for (int j = 0; j < 4; ++j)
#pragma unroll
            for (int l = 0; l < 4; ++l) acc[i][j][l] = 0.f;

    const int NC = K / KT;

    // prologue: stages 0 and 1
#pragma unroll
    for (int s = 0; s < 2; ++s) {
        const uint32_t sb = smb + s * STAGE_BYTES;
        const int k0 = s * KT;
#pragma unroll
        for (int i = 0; i < 4; ++i) {
            const int r = r0 + 32 * i;
            cpa16(sb + stg_off + i * 32 * PROW,
                  Ag + (size_t)r * K + k0 + s4);
            cpa16(sb + A_BYTES + stg_off + i * 32 * PROW,
                  Bg + (size_t)r * K + k0 + s4);
        }
        cpa_commit();
    }

    const int tb = tig * 32;

    for (int c = 0; c < NC; ++c) {
        cpa_wait1();
        __syncthreads();

        if (c + 2 < NC) {
            const uint32_t sb = smb + ((c + 2) % NSTAGE) * STAGE_BYTES;
            const int k0 = (c + 2) * KT;
#pragma unroll
            for (int i = 0; i < 4; ++i) {
                const int r = r0 + 32 * i;
                cpa16(sb + stg_off + i * 32 * PROW,
                      Ag + (size_t)r * K + k0 + s4);
                cpa16(sb + A_BYTES + stg_off + i * 32 * PROW,
                      Bg + (size_t)r * K + k0 + s4);
            }
        }
        cpa_commit();

        const char* sa = smem + (c % NSTAGE) * STAGE_BYTES;
        const char* sbuf = sa + A_BYTES;
#pragma unroll
        for (int hf = 0; hf < 2; ++hf) {          // kk pairs {0,1},{2,3}
            const int hb = hf * 16;
#pragma unroll
            for (int mp = 0; mp < 2; ++mp) {      // mf pairs: low pressure
                uint4 aL0, aH0, aL1, aH1;
                {
                    const int m0 = warp_m + (mp * 2 + 0) * 16 + group;
                    const int m1 = warp_m + (mp * 2 + 1) * 16 + group;
                    aL0 = *(const uint4*)(sa + m0 * PROW + tb + hb);
                    aH0 = *(const uint4*)(sa + (m0 + 8) * PROW + tb + hb);
                    aL1 = *(const uint4*)(sa + m1 * PROW + tb + hb);
                    aH1 = *(const uint4*)(sa + (m1 + 8) * PROW + tb + hb);
                }
#pragma unroll
                for (int nf = 0; nf < 4; ++nf) {
                    const uint4 bv = *(const uint4*)(sbuf +
                        (warp_n + nf * 8 + group) * PROW + tb + hb);
                    const int mf0 = mp * 2, mf1 = mp * 2 + 1;
                    mma8(acc[mf0][nf][0], acc[mf0][nf][1],
                         acc[mf0][nf][2], acc[mf0][nf][3],
                         aL0.x, aH0.x, aL0.y, aH0.y, bv.x, bv.y);
                    mma8(acc[mf0][nf][0], acc[mf0][nf][1],
                         acc[mf0][nf][2], acc[mf0][nf][3],
                         aL0.z, aH0.z, aL0.w, aH0.w, bv.z, bv.w);
                    mma8(acc[mf1][nf][0], acc[mf1][nf][1],
                         acc[mf1][nf][2], acc[mf1][nf][3],
                         aL1.x, aH1.x, aL1.y, aH1.y, bv.x, bv.y);
                    mma8(acc[mf1][nf][0], acc[mf1][nf][1],
                         acc[mf1][nf][2], acc[mf1][nf][3],
                         aL1.z, aH1.z, aL1.w, aH1.w, bv.z, bv.w);
                }
            }
        }
        __syncthreads();
    }

    // ---------------------------- epilogue --------------------------------
    if (!mode) {
        float* __restrict__ C = (sel == 0) ? g_v : g_q;
#pragma unroll
        for (int nf = 0; nf < 4; ++nf) {
            const int gn = bn + warp_n + nf * 8 + 2 * tig;
            const float b0 = __ldg(&bias[gn]);
            const float b1 = __ldg(&bias[gn + 1]);
#pragma unroll
            for (int mf = 0; mf < 4; ++mf) {
                const int gm = bm + warp_m + mf * 16 + group;
                float2 lo, hi;
                lo.x = fmaxf(acc[mf][nf][0] + b0, 0.f);
                lo.y = fmaxf(acc[mf][nf][1] + b1, 0.f);
                hi.x = fmaxf(acc[mf][nf][2] + b0, 0.f);
                hi.y = fmaxf(acc[mf][nf][3] + b1, 0.f);
                *(float2*)(C + (size_t)gm * Ntot + gn)       = lo;
                *(float2*)(C + (size_t)(gm + 8) * Ntot + gn) = hi;
            }
        }
    } else {
        const int h = blockIdx.y;
        const float hb = __ldg(&h_bias[h]);
        float* __restrict__ C = Cp + ((size_t)(z * HO_ + h) * NV_) * NQ_;
#pragma unroll
        for (int nf = 0; nf < 4; ++nf) {
            const int qn = warp_n + nf * 8 + 2 * tig;
#pragma unroll
            for (int mf = 0; mf < 4; ++mf) {
                const int vm = bm + warp_m + mf * 16 + group;
                float2 lo, hi;
                lo.x = acc[mf][nf][0] + hb;
                lo.y = acc[mf][nf][1] + hb;
                hi.x = acc[mf][nf][2] + hb;
                hi.y = acc[mf][nf][3] + hb;
                *(float2*)(C + (size_t)vm * NQ_ + qn)       = lo;
                *(float2*)(C + (size_t)(vm + 8) * NQ_ + qn) = hi;
            }
        }
    }
}

// ---------------------------------------------------------------------------
// inputs: v, q, Wv, bv, Wq, bq, h_mat, h_bias ; output fp32 (32,8,512,128)
// ---------------------------------------------------------------------------
static inline unsigned pgrid(size_t n) { return (unsigned)((n / 4 + 255) / 256); }

extern "C" void kernel_launch(void* const* d_in, const int* in_sizes, int n_in,
                              void* d_out, int out_size)
{
    const float* v      = (const float*)d_in[0];
    const float* q      = (const float*)d_in[1];
    const float* Wv     = (const float*)d_in[2];
    const float* bv     = (const float*)d_in[3];
    const float* Wq     = (const float*)d_in[4];
    const float* bq     = (const float*)d_in[5];
    const float* h_mat  = (const float*)d_in[6];
    const float* h_bias = (const float*)d_in[7];
    float* out = (float*)d_out;

    cudaFuncSetAttribute(gemm_mma, cudaFuncAttributeMaxDynamicSharedMemorySize,
                         SMEM_BYTES);

    const size_t n_v  = (size_t)B_ * NV_ * VD_;
    const size_t n_q  = (size_t)B_ * NQ_ * QD_;
    const size_t n_wv = (size_t)HK_ * VD_;
    const size_t n_wq = (size_t)HK_ * QD_;
    const size_t n_gv = (size_t)B_ * NV_ * HK_;
    const size_t n_qh = (size_t)B_ * HO_ * NQ_ * HK_;

    // pre-convert + permute inputs
    perm_cvt<<<pgrid(n_v),  256>>>(v,  0, n_v);
    perm_cvt<<<pgrid(n_q),  256>>>(q,  1, n_q);
    perm_cvt<<<pgrid(n_wv), 256>>>(Wv, 2, n_wv);
    perm_cvt<<<pgrid(n_wq), 256>>>(Wq, 3, n_wq);

    // G1: v-proj -> g_v (plain)  M=16384 N=1536 K=2048
    gemm_mma<<<dim3((B_ * NV_) / BM, HK_ / BN, 1), 256, SMEM_BYTES>>>(
        bv, nullptr, nullptr, HK_, VD_, 0);
    // permute+cvt g_v -> g_vtp
    perm_cvt<<<pgrid(n_gv), 256>>>(nullptr, 4, n_gv);

    // G2: q-proj -> g_q (plain)  M=4096 N=1536 K=1024
    gemm_mma<<<dim3((B_ * NQ_) / BM, HK_ / BN, 1), 256, SMEM_BYTES>>>(
        bq, nullptr, nullptr, HK_, QD_, 1);
    // g_qh = perm(cvt(g_q * h_mat)) for all 8 heads
    qh_cvt<<<pgrid(n_qh), 256>>>(h_mat);

    // G3: bilinear -> out  per z: M=512 N=1024(8h x 128q) K=1536
    gemm_mma<<<dim3(NV_ / BM, (HO_ * NQ_) / BN, B_), 256, SMEM_BYTES>>>(
        nullptr, h_bias, out, HO_ * NQ_, HK_, 2);
}